// round 2
// baseline (speedup 1.0000x reference)
#include <cuda_runtime.h>
#include <math.h>

#define T 4096
#define E 300
#define HID 512
#define G4 2048          // 4*HID
#define TAGS 12
#define NEGV -10000.0f
#define NBD 64           // persistent blocks per direction in LSTM kernel

// ---------------- static device scratch (no allocations allowed) ----------------
__device__ float d_xg[2][T * G4];          // 2 x 32 MB: precomputed input projections
__device__ float d_Hs[2][T * HID];         // 2 x 8 MB : per-step hidden states
__device__ unsigned int d_tag[2][T][NBD];  // per-(dir,step,producer) release tags
__device__ float d_feats[T * TAGS];
__device__ unsigned long long d_bp[T];     // packed backpointers: 12 nibbles per step

// ---------------- reset tags (graph replays reuse state) ----------------
__global__ void init_kernel() {
    int i = blockIdx.x * blockDim.x + threadIdx.x;
    if (i < 2 * T * NBD) ((unsigned int*)d_tag)[i] = 0u;
}

// ---------------- xg = emb[sentence] @ Wih^T + (bih + bhh) ----------------
// grid (T/32, 2048/256), block 256. Each block: 32 timesteps x 256 rows.
__global__ void __launch_bounds__(256) xg_kernel(
    int dir,
    const int*   __restrict__ sent,
    const float* __restrict__ embt,
    const float* __restrict__ Wih,
    const float* __restrict__ bih,
    const float* __restrict__ bhh)
{
    __shared__ __align__(16) float es[E * 32];   // es[k*32 + t]
    int t0 = blockIdx.x * 32;
    for (int i = threadIdx.x; i < 32 * E; i += 256) {
        int tt = i / E, k = i - tt * E;
        es[k * 32 + tt] = embt[(long long)sent[t0 + tt] * E + k];
    }
    __syncthreads();

    int r = blockIdx.y * 256 + threadIdx.x;
    const float* w = Wih + (long long)r * E;
    float bias = bih[r] + bhh[r];
    float acc[32];
#pragma unroll
    for (int t = 0; t < 32; t++) acc[t] = bias;

    for (int k = 0; k < E; k++) {
        float wv = __ldg(w + k);
        const float4* e4 = (const float4*)(es + k * 32);
#pragma unroll
        for (int q = 0; q < 8; q++) {
            float4 e = e4[q];
            acc[4 * q + 0] += wv * e.x;
            acc[4 * q + 1] += wv * e.y;
            acc[4 * q + 2] += wv * e.z;
            acc[4 * q + 3] += wv * e.w;
        }
    }
    float* xg = d_xg[dir];
#pragma unroll
    for (int t = 0; t < 32; t++)
        xg[(long long)(t0 + t) * G4 + r] = acc[t];
}

// ---------------- persistent BiLSTM recurrence ----------------
// 128 blocks (64 fwd, 64 bwd), 256 threads each; all co-resident (<=148 SMs).
// Block b owns 8 hidden units u in [8b, 8b+8) -> 32 Whh gate rows.
// Warp w (0..7): column chunk [64w, 64w+64). Lane l: local gate row l
// (gate g = l>>3, unit = l&7). 64 fp32 weights per thread in registers.
// Per step: broadcast-LDS partial dots -> smem part[8][32] -> warp 0 reduces,
// activates (one MUFU chain per lane), lane 0 stores the 8-float h slice and
// st.release's a tag. All warps poll all 64 tags (ld.acquire u64 pairs),
// reload h (ldcg) into the other smem buffer. 2 syncthreads per step.
__global__ void __launch_bounds__(256, 1) lstm_kernel(
    const float* __restrict__ Whh_f,
    const float* __restrict__ Whh_b)
{
    const int bx  = blockIdx.x;
    const int dir = bx >> 6;
    const int b   = bx & 63;
    const float* Whh = dir ? Whh_b : Whh_f;
    const float* xg  = d_xg[dir];
    float* Hst = d_Hs[dir];
    unsigned int (*tags)[NBD] = d_tag[dir];

    const int tid = threadIdx.x;
    const int w = tid >> 5, l = tid & 31;
    const int grow = ((l >> 3) << 9) + b * 8 + (l & 7);   // global gate row

    // weights: 64 fp32 per thread
    float wreg[64];
    {
        const float4* wp = (const float4*)(Whh + (long long)grow * HID + w * 64);
#pragma unroll
        for (int i = 0; i < 16; i++) {
            float4 v = wp[i];
            wreg[4 * i + 0] = v.x; wreg[4 * i + 1] = v.y;
            wreg[4 * i + 2] = v.z; wreg[4 * i + 3] = v.w;
        }
    }

    __shared__ __align__(16) float h_buf[2][HID];
    __shared__ float part[8][32];

    float c = 0.f;          // cell state, lanes 0-7 of warp 0
    float xg_cur = 0.f;

    // init
    ((float2*)h_buf[0])[tid] = make_float2(0.f, 0.f);
    if (w == 0) {
        int t0 = dir ? (T - 1) : 0;
        xg_cur = xg[(long long)t0 * G4 + grow];
    }
    __syncthreads();

    const unsigned long long TGT = 0x0000000100000001ULL;

    for (int s = 0; s < T; s++) {
        const int t   = dir ? (T - 1 - s) : s;
        const int buf = s & 1;

        // ---- partial dot: lane row x 64-col chunk, h broadcast from smem ----
        {
            float a0 = 0.f, a1 = 0.f, a2 = 0.f, a3 = 0.f;
            const float4* h4 = (const float4*)(h_buf[buf] + (w << 6));
#pragma unroll
            for (int i = 0; i < 16; i++) {
                float4 hv = h4[i];
                a0 += wreg[4 * i + 0] * hv.x;
                a1 += wreg[4 * i + 1] * hv.y;
                a2 += wreg[4 * i + 2] * hv.z;
                a3 += wreg[4 * i + 3] * hv.w;
            }
            part[w][l] = (a0 + a1) + (a2 + a3);
        }
        __syncthreads();   // A: all partials in smem

        if (w == 0) {
            float sum = xg_cur;
#pragma unroll
            for (int ww = 0; ww < 8; ww++) sum += part[ww][l];

            // prefetch next step's xg while the rest of the chain runs
            if (s + 1 < T) {
                int tn = dir ? (t - 1) : (t + 1);
                xg_cur = __ldcg(xg + (long long)tn * G4 + grow);
            }

            // activation: lanes 16-23 (gate g) use tanh, others sigmoid
            bool is_tanh = (l >= 16) & (l < 24);
            float xa = is_tanh ? (2.f * sum) : sum;
            float e  = __expf(-xa);
            float sg = __fdividef(1.f, 1.f + e);
            float act = is_tanh ? (2.f * sg - 1.f) : sg;

            int u = l & 7;
            float iv = __shfl_sync(0xffffffffu, act, u);
            float fv = __shfl_sync(0xffffffffu, act, u + 8);
            float gv = __shfl_sync(0xffffffffu, act, u + 16);
            float ov = __shfl_sync(0xffffffffu, act, u + 24);

            float hh = 0.f;
            if (l < 8) {
                c = fv * c + iv * gv;
                float ec = __expf(-2.f * c);
                float th = __fdividef(2.f, 1.f + ec) - 1.f;
                hh = ov * th;
            }
            // gather 8 h values into lane 0, single-thread store + release tag
            float4 A, B;
            A.x = __shfl_sync(0xffffffffu, hh, 0);
            A.y = __shfl_sync(0xffffffffu, hh, 1);
            A.z = __shfl_sync(0xffffffffu, hh, 2);
            A.w = __shfl_sync(0xffffffffu, hh, 3);
            B.x = __shfl_sync(0xffffffffu, hh, 4);
            B.y = __shfl_sync(0xffffffffu, hh, 5);
            B.z = __shfl_sync(0xffffffffu, hh, 6);
            B.w = __shfl_sync(0xffffffffu, hh, 7);
            if (l == 0) {
                float4* hp = (float4*)(Hst + (long long)t * HID + b * 8);
                hp[0] = A;
                hp[1] = B;
                unsigned int* tp = &tags[t][b];
                asm volatile("st.release.gpu.global.u32 [%0], %1;"
                             :: "l"(tp), "r"(1u) : "memory");
            }
        }

        if (s == T - 1) break;

        // ---- poll all 64 producer tags (2 per lane, u64 acquire loads) ----
        {
            const unsigned long long* tp =
                (const unsigned long long*)(&tags[t][0]) + l;
            unsigned long long v;
            do {
                asm volatile("ld.acquire.gpu.global.u64 %0, [%1];"
                             : "=l"(v) : "l"(tp) : "memory");
            } while (!__all_sync(0xffffffffu, v == TGT));
        }

        // ---- reload full h(t) into the other buffer ----
        {
            float2 hv = __ldcg((const float2*)(Hst + (long long)t * HID) + tid);
            ((float2*)h_buf[buf ^ 1])[tid] = hv;
        }
        __syncthreads();   // B: h ready, part free for reuse
    }
}

// ---------------- feats = [h_f, h_b] @ W_out^T + b_out ----------------
__global__ void __launch_bounds__(128) feats_kernel(
    const float* __restrict__ W_out,
    const float* __restrict__ b_out)
{
    __shared__ __align__(16) float hb[2 * HID];
    int tid = threadIdx.x;
    int r = tid >> 3, cs = tid & 7;

    for (int tt = 0; tt < 32; tt++) {
        int t = blockIdx.x * 32 + tt;
        __syncthreads();
        ((float4*)hb)[tid]       = ((const float4*)(d_Hs[0] + (long long)t * HID))[tid];
        ((float4*)hb)[128 + tid] = ((const float4*)(d_Hs[1] + (long long)t * HID))[tid];
        __syncthreads();
        if (tid < 96) {
            const float4* wv = (const float4*)(W_out + r * 1024 + cs * 128);
            const float4* hv = (const float4*)(hb + cs * 128);
            float s0 = 0.f, s1 = 0.f, s2 = 0.f, s3 = 0.f;
#pragma unroll
            for (int i = 0; i < 32; i++) {
                float4 a = __ldg(wv + i);
                float4 bq = hv[i];
                s0 += a.x * bq.x; s1 += a.y * bq.y;
                s2 += a.z * bq.z; s3 += a.w * bq.w;
            }
            float sum = (s0 + s1) + (s2 + s3);
#pragma unroll
            for (int o = 4; o >= 1; o >>= 1)
                sum += __shfl_down_sync(0xffffffffu, sum, o);
            if (cs == 0)
                d_feats[t * TAGS + r] = sum + b_out[r];
        }
    }
}

// ---------------- Viterbi: forward scan + packed backtrace ----------------
__global__ void viterbi_kernel(const float* __restrict__ trans,
                               float* __restrict__ out)
{
    __shared__ unsigned long long bps[T];
    int l = threadIdx.x;

    float tr[TAGS];
    if (l < TAGS) {
#pragma unroll
        for (int p = 0; p < TAGS; p++) tr[p] = trans[l * TAGS + p];
    } else {
#pragma unroll
        for (int p = 0; p < TAGS; p++) tr[p] = 0.f;
    }

    float fv = (l == 10) ? 0.f : NEGV;   // START = 10
    float featnext = (l < TAGS) ? d_feats[l] : 0.f;

    for (int t = 0; t < T; t++) {
        float feat = featnext;
        if (t + 1 < T && l < TAGS) featnext = d_feats[(t + 1) * TAGS + l];

        float m = -3.4e38f; int am = 0;
#pragma unroll
        for (int p = 0; p < TAGS; p++) {
            float v = __shfl_sync(0xffffffffu, fv, p) + tr[p];
            if (v > m) { m = v; am = p; }
        }
        unsigned lo = (l < 8)              ? ((unsigned)am << (4 * l))       : 0u;
        unsigned hi = (l >= 8 && l < TAGS) ? ((unsigned)am << (4 * (l - 8))) : 0u;
        lo = __reduce_add_sync(0xffffffffu, lo);
        hi = __reduce_add_sync(0xffffffffu, hi);
        if (l == 0) d_bp[t] = ((unsigned long long)hi << 32) | lo;

        fv = m + feat;
    }

    float term;
    if (l < TAGS) term = fv + trans[11 * TAGS + l];
    else          term = -3.4e38f;
    if (l == 11 || l == 10) term = NEGV;

    int best = 0; float sc = -3.4e38f;
#pragma unroll
    for (int p = 0; p < TAGS; p++) {
        float v = __shfl_sync(0xffffffffu, term, p);
        if (v > sc) { sc = v; best = p; }
    }

    for (int i = l; i < T; i += 32) bps[i] = d_bp[i];
    __syncwarp();

    if (l == 0) {
        out[0] = sc;
        out[T] = (float)best;            // path[T-1]
        int tag = best;
        for (int t = T - 1; t >= 1; t--) {
            int prev = (int)((bps[t] >> (4 * tag)) & 15ull);
            out[t] = (float)prev;        // path[t-1] = chain[t]
            tag = prev;
        }
    }
}

// ---------------- launch ----------------
extern "C" void kernel_launch(void* const* d_in, const int* in_sizes, int n_in,
                              void* d_out, int out_size)
{
    const int*   sent  = (const int*)d_in[0];
    const float* embt  = (const float*)d_in[1];
    const float* Wih_f = (const float*)d_in[2];
    const float* Whh_f = (const float*)d_in[3];
    const float* bih_f = (const float*)d_in[4];
    const float* bhh_f = (const float*)d_in[5];
    const float* Wih_b = (const float*)d_in[6];
    const float* Whh_b = (const float*)d_in[7];
    const float* bih_b = (const float*)d_in[8];
    const float* bhh_b = (const float*)d_in[9];
    const float* W_out = (const float*)d_in[10];
    const float* b_out = (const float*)d_in[11];
    const float* trans = (const float*)d_in[12];
    float* out = (float*)d_out;

    init_kernel<<<512, 1024>>>();
    dim3 g(T / 32, G4 / 256);
    xg_kernel<<<g, 256>>>(0, sent, embt, Wih_f, bih_f, bhh_f);
    xg_kernel<<<g, 256>>>(1, sent, embt, Wih_b, bih_b, bhh_b);
    lstm_kernel<<<2 * NBD, 256>>>(Whh_f, Whh_b);
    feats_kernel<<<128, 128>>>(W_out, b_out);
    viterbi_kernel<<<1, 32>>>(trans, out);
}

// round 5
// speedup vs baseline: 2.6815x; 2.6815x over previous
#include <cuda_runtime.h>
#include <math.h>

#define T 4096
#define E 300
#define HID 512
#define G4 2048          // 4*HID
#define TAGS 12
#define NEGV -10000.0f
#define NB 32            // persistent blocks per direction in LSTM kernel

// ---------------- static device scratch (no allocations allowed) ----------------
__device__ float d_xg[2][T * G4];          // 2 x 32 MB: precomputed input projections
__device__ float d_Hs[2][T * HID];         // 2 x 8 MB : per-step hidden states
__device__ unsigned int d_tag[2][T][NB];   // per-(dir,step,producer) release tags
__device__ float d_feats[T * TAGS];
__device__ unsigned long long d_bp[T];     // packed backpointers: 12 nibbles per step

// ---------------- zero tags (graph replays reuse state) ----------------
__global__ void init_kernel() {
    int i = blockIdx.x * 1024 + threadIdx.x;
    if (i < 2 * T * NB) ((unsigned int*)d_tag)[i] = 0u;
}

// ---------------- xg = emb[sentence] @ Wih^T + (bih + bhh) ----------------
// grid (T/32, 2048/256), block 256. Each block: 32 timesteps x 256 rows.
__global__ void __launch_bounds__(256) xg_kernel(
    int dir,
    const int*   __restrict__ sent,
    const float* __restrict__ embt,
    const float* __restrict__ Wih,
    const float* __restrict__ bih,
    const float* __restrict__ bhh)
{
    __shared__ __align__(16) float es[E * 32];   // es[k*32 + t]
    int t0 = blockIdx.x * 32;
    for (int i = threadIdx.x; i < 32 * E; i += 256) {
        int tt = i / E, k = i - tt * E;
        es[k * 32 + tt] = embt[(long long)sent[t0 + tt] * E + k];
    }
    __syncthreads();

    int r = blockIdx.y * 256 + threadIdx.x;
    const float* w = Wih + (long long)r * E;
    float bias = bih[r] + bhh[r];
    float acc[32];
#pragma unroll
    for (int t = 0; t < 32; t++) acc[t] = bias;

    for (int k = 0; k < E; k++) {
        float wv = __ldg(w + k);
        const float4* e4 = (const float4*)(es + k * 32);
#pragma unroll
        for (int q = 0; q < 8; q++) {
            float4 e = e4[q];
            acc[4 * q + 0] += wv * e.x;
            acc[4 * q + 1] += wv * e.y;
            acc[4 * q + 2] += wv * e.z;
            acc[4 * q + 3] += wv * e.w;
        }
    }
    float* xg = d_xg[dir];
#pragma unroll
    for (int t = 0; t < 32; t++)
        xg[(long long)(t0 + t) * G4 + r] = acc[t];
}

// ---------------- persistent BiLSTM recurrence ----------------
// 64 blocks (32 fwd, 32 bwd), 256 threads; all co-resident.
// Block b owns 16 hidden units -> 64 Whh gate rows (128 fp32 regs/thread).
// Warp w: col chunk cc=w>>1 (128 cols), local gate row lr=(w&1)*32+l.
// Per step:
//   all warps: scalar float4 partial dots -> part[4][64] -> syncA
//   warp 0: lanes<16 reduce + activations; shfl-gather slice to lane 0;
//           lane 0 stores 4xfloat4 h slice then st.release.gpu tag  (R2-proven)
//   warp 1: each lane ld.acquire.gpu one tag (32 tags = one 128B line),
//           loop until all set; syncwarp; reload full h(t) (4 ldcg float4
//           per lane) into h_sh
//   syncB  -> next step's dot reads h_sh
__global__ void __launch_bounds__(256, 1) lstm_kernel(
    const float* __restrict__ Whh_f,
    const float* __restrict__ Whh_b)
{
    const int bx  = blockIdx.x;
    const int dir = bx >> 5;
    const int b   = bx & 31;
    const float* Whh = dir ? Whh_b : Whh_f;
    const float* xg  = d_xg[dir];
    float* Hst = d_Hs[dir];
    unsigned int (*tags)[NB] = d_tag[dir];

    const int tid = threadIdx.x;
    const int w = tid >> 5, l = tid & 31;
    const int cc = w >> 1;                  // 0..3 column chunk (128 cols)
    const int lr = (w & 1) * 32 + l;        // 0..63 local gate row
    const int grow = ((lr >> 4) << 9) + b * 16 + (lr & 15);  // global gate row

    // weights: 128 fp32 per thread in registers
    float wreg[128];
    {
        const float4* wp = (const float4*)(Whh + (long long)grow * HID + cc * 128);
#pragma unroll
        for (int i = 0; i < 32; i++) {
            float4 v = wp[i];
            wreg[4 * i + 0] = v.x; wreg[4 * i + 1] = v.y;
            wreg[4 * i + 2] = v.z; wreg[4 * i + 3] = v.w;
        }
    }

    __shared__ __align__(16) float h_sh[HID];
    __shared__ float part[4][64];

    float c = 0.f;                 // cell state (warp 0 lanes 0-15)
    float xgv[4] = {0.f, 0.f, 0.f, 0.f};

    h_sh[tid] = 0.f;
    h_sh[tid + 256] = 0.f;
    if (w == 0 && l < 16) {
        int t0 = dir ? (T - 1) : 0;
#pragma unroll
        for (int g = 0; g < 4; g++)
            xgv[g] = xg[(long long)t0 * G4 + (g << 9) + b * 16 + l];
    }
    __syncthreads();

    for (int s = 0; s < T; s++) {
        const int t = dir ? (T - 1 - s) : s;

        // ---- partial dot: lane gate-row x 128-col chunk (scalar FFMA) ----
        {
            float a0 = 0.f, a1 = 0.f, a2 = 0.f, a3 = 0.f;
            const float4* h4 = (const float4*)(h_sh + (cc << 7));
#pragma unroll
            for (int i = 0; i < 32; i++) {
                float4 hv = h4[i];   // broadcast LDS.128 (uniform address)
                a0 += wreg[4 * i + 0] * hv.x;
                a1 += wreg[4 * i + 1] * hv.y;
                a2 += wreg[4 * i + 2] * hv.z;
                a3 += wreg[4 * i + 3] * hv.w;
            }
            part[cc][lr] = (a0 + a1) + (a2 + a3);
        }
        __syncthreads();   // A: all partials in smem

        if (w == 0) {
            float hh = 0.f;
            if (l < 16) {
                float g0 = part[0][l]      + part[1][l]      + part[2][l]      + part[3][l]      + xgv[0];
                float g1 = part[0][16 + l] + part[1][16 + l] + part[2][16 + l] + part[3][16 + l] + xgv[1];
                float g2 = part[0][32 + l] + part[1][32 + l] + part[2][32 + l] + part[3][32 + l] + xgv[2];
                float g3 = part[0][48 + l] + part[1][48 + l] + part[2][48 + l] + part[3][48 + l] + xgv[3];

                float ig = __fdividef(1.f, 1.f + __expf(-g0));
                float fg = __fdividef(1.f, 1.f + __expf(-g1));
                float og = __fdividef(1.f, 1.f + __expf(-g3));
                float tg = __fdividef(2.f, 1.f + __expf(-2.f * g2)) - 1.f;
                c = fg * c + ig * tg;
                float th = __fdividef(2.f, 1.f + __expf(-2.f * c)) - 1.f;
                hh = og * th;
            }
            // gather the 16-float slice to lane 0 (all 32 lanes convergent)
            float hv[16];
#pragma unroll
            for (int k = 0; k < 16; k++)
                hv[k] = __shfl_sync(0xffffffffu, hh, k);
            if (l == 0) {
                float4* hp = (float4*)(Hst + (long long)t * HID + b * 16);
                hp[0] = make_float4(hv[0],  hv[1],  hv[2],  hv[3]);
                hp[1] = make_float4(hv[4],  hv[5],  hv[6],  hv[7]);
                hp[2] = make_float4(hv[8],  hv[9],  hv[10], hv[11]);
                hp[3] = make_float4(hv[12], hv[13], hv[14], hv[15]);
                asm volatile("st.release.gpu.global.u32 [%0], %1;"
                             :: "l"(&tags[t][b]), "r"(1u) : "memory");
            }
            // prefetch next step's xg (a full step of latency slack)
            if (l < 16 && s + 1 < T) {
                int tn = dir ? (t - 1) : (t + 1);
#pragma unroll
                for (int g = 0; g < 4; g++)
                    xgv[g] = __ldcg(xg + (long long)tn * G4 + (g << 9) + b * 16 + l);
            }
        } else if (w == 1 && s + 1 < T) {
            // ---- acquire all 32 producer tags (one 128B line) ----
            const unsigned int* tp = &tags[t][l];
            unsigned int v;
            do {
                asm volatile("ld.acquire.gpu.global.u32 %0, [%1];"
                             : "=r"(v) : "l"(tp) : "memory");
            } while (!__all_sync(0xffffffffu, v == 1u));
            __syncwarp();   // bar.warp.sync: cross-lane memory ordering

            // ---- reload full h(t): 4 coalesced float4 loads per lane ----
            const float4* hp4 = (const float4*)(Hst + (long long)t * HID);
            float4 r0 = __ldcg(hp4 + l);
            float4 r1 = __ldcg(hp4 + 32 + l);
            float4 r2 = __ldcg(hp4 + 64 + l);
            float4 r3 = __ldcg(hp4 + 96 + l);
            float4* hs4 = (float4*)h_sh;
            hs4[l]      = r0;
            hs4[32 + l] = r1;
            hs4[64 + l] = r2;
            hs4[96 + l] = r3;
        }
        __syncthreads();   // B: h(t) staged in smem for next step
    }
}

// ---------------- feats = [h_f, h_b] @ W_out^T + b_out ----------------
__global__ void __launch_bounds__(128) feats_kernel(
    const float* __restrict__ W_out,
    const float* __restrict__ b_out)
{
    __shared__ __align__(16) float hb[2 * HID];
    int tid = threadIdx.x;
    int r = tid >> 3, cs = tid & 7;

    for (int tt = 0; tt < 32; tt++) {
        int t = blockIdx.x * 32 + tt;
        __syncthreads();
        ((float4*)hb)[tid]       = ((const float4*)(d_Hs[0] + (long long)t * HID))[tid];
        ((float4*)hb)[128 + tid] = ((const float4*)(d_Hs[1] + (long long)t * HID))[tid];
        __syncthreads();
        if (tid < 96) {
            const float4* wv = (const float4*)(W_out + r * 1024 + cs * 128);
            const float4* hv = (const float4*)(hb + cs * 128);
            float s0 = 0.f, s1 = 0.f, s2 = 0.f, s3 = 0.f;
#pragma unroll
            for (int i = 0; i < 32; i++) {
                float4 a = __ldg(wv + i);
                float4 bq = hv[i];
                s0 += a.x * bq.x; s1 += a.y * bq.y;
                s2 += a.z * bq.z; s3 += a.w * bq.w;
            }
            float sum = (s0 + s1) + (s2 + s3);
#pragma unroll
            for (int o = 4; o >= 1; o >>= 1)
                sum += __shfl_down_sync(0xffffffffu, sum, o);
            if (cs == 0)
                d_feats[t * TAGS + r] = sum + b_out[r];
        }
    }
}

// ---------------- Viterbi: forward scan + packed backtrace ----------------
__global__ void viterbi_kernel(const float* __restrict__ trans,
                               float* __restrict__ out)
{
    __shared__ unsigned long long bps[T];
    int l = threadIdx.x;

    float tr[TAGS];
    if (l < TAGS) {
#pragma unroll
        for (int p = 0; p < TAGS; p++) tr[p] = trans[l * TAGS + p];
    } else {
#pragma unroll
        for (int p = 0; p < TAGS; p++) tr[p] = 0.f;
    }

    float fv = (l == 10) ? 0.f : NEGV;   // START = 10
    float featnext = (l < TAGS) ? d_feats[l] : 0.f;

    for (int t = 0; t < T; t++) {
        float feat = featnext;
        if (t + 1 < T && l < TAGS) featnext = d_feats[(t + 1) * TAGS + l];

        float m = -3.4e38f; int am = 0;
#pragma unroll
        for (int p = 0; p < TAGS; p++) {
            float v = __shfl_sync(0xffffffffu, fv, p) + tr[p];
            if (v > m) { m = v; am = p; }
        }
        unsigned lo = (l < 8)              ? ((unsigned)am << (4 * l))       : 0u;
        unsigned hi = (l >= 8 && l < TAGS) ? ((unsigned)am << (4 * (l - 8))) : 0u;
        lo = __reduce_add_sync(0xffffffffu, lo);
        hi = __reduce_add_sync(0xffffffffu, hi);
        if (l == 0) d_bp[t] = ((unsigned long long)hi << 32) | lo;

        fv = m + feat;
    }

    float term;
    if (l < TAGS) term = fv + trans[11 * TAGS + l];
    else          term = -3.4e38f;
    if (l == 11 || l == 10) term = NEGV;

    int best = 0; float sc = -3.4e38f;
#pragma unroll
    for (int p = 0; p < TAGS; p++) {
        float v = __shfl_sync(0xffffffffu, term, p);
        if (v > sc) { sc = v; best = p; }
    }

    for (int i = l; i < T; i += 32) bps[i] = d_bp[i];
    __syncwarp();

    if (l == 0) {
        out[0] = sc;
        out[T] = (float)best;            // path[T-1]
        int tag = best;
        for (int t = T - 1; t >= 1; t--) {
            int prev = (int)((bps[t] >> (4 * tag)) & 15ull);
            out[t] = (float)prev;        // path[t-1] = chain[t]
            tag = prev;
        }
    }
}

// ---------------- launch ----------------
extern "C" void kernel_launch(void* const* d_in, const int* in_sizes, int n_in,
                              void* d_out, int out_size)
{
    const int*   sent  = (const int*)d_in[0];
    const float* embt  = (const float*)d_in[1];
    const float* Wih_f = (const float*)d_in[2];
    const float* Whh_f = (const float*)d_in[3];
    const float* bih_f = (const float*)d_in[4];
    const float* bhh_f = (const float*)d_in[5];
    const float* Wih_b = (const float*)d_in[6];
    const float* Whh_b = (const float*)d_in[7];
    const float* bih_b = (const float*)d_in[8];
    const float* bhh_b = (const float*)d_in[9];
    const float* W_out = (const float*)d_in[10];
    const float* b_out = (const float*)d_in[11];
    const float* trans = (const float*)d_in[12];
    float* out = (float*)d_out;

    init_kernel<<<256, 1024>>>();
    dim3 g(T / 32, G4 / 256);
    xg_kernel<<<g, 256>>>(0, sent, embt, Wih_f, bih_f, bhh_f);
    xg_kernel<<<g, 256>>>(1, sent, embt, Wih_b, bih_b, bhh_b);
    lstm_kernel<<<2 * NB, 256>>>(Whh_f, Whh_b);
    feats_kernel<<<128, 128>>>(W_out, b_out);
    viterbi_kernel<<<1, 32>>>(trans, out);
}